// round 4
// baseline (speedup 1.0000x reference)
#include <cuda_runtime.h>
#include <cuda_bf16.h>
#include <math.h>

#define BS   16
#define NA   8400
#define NMAX 64
#define NC   80
#define TOPK 13
#define EPSF 1e-9f
#define PIF  3.14159265358979323846f

// Output layout (flattened, reference return order, all f32)
#define LAB_OFF 0
#define CIR_OFF (BS*NA)                 // 134400
#define SC_OFF  (CIR_OFF + BS*NA*3)     // 537600
#define FG_OFF  (SC_OFF  + BS*NA*NC)    // 11289600
#define TGT_OFF (FG_OFF  + BS*NA)       // 11424000

// ---- scratch (zero at module load; self-resetting across graph replays) ----
__device__ int          g_cnt [BS*NA];     // claims per anchor      (kC resets to 0)
__device__ int          g_maxj[BS*NA];     // max(NMAX-j) of claims  (kC resets to 0)
__device__ int          g_tgt [BS*NA];
__device__ int          g_lab [BS*NA];     // label or -1
__device__ float        g_alpos[BS*NA];
__device__ unsigned int g_posal[BS*NMAX];  // zeroed by kAB each run
__device__ unsigned int g_posov[BS*NMAX];  // zeroed by kAB each run

__device__ __forceinline__ float circle_iou_f(float gx, float gy, float gr,
                                              float px, float py, float pr)
{
    float ddx = gx - px, ddy = gy - py;
    float d  = sqrtf(ddx*ddx + ddy*ddy + EPSF);
    float r1 = gr, r2 = pr;
    float a1 = PIF*r1*r1, a2 = PIF*r2*r2;
    float d2 = d*d;
    float cos1 = fminf(fmaxf((d2 + r1*r1 - r2*r2) / (2.f*d*r1 + EPSF), -1.f), 1.f);
    float cos2 = fminf(fmaxf((d2 + r2*r2 - r1*r1) / (2.f*d*r2 + EPSF), -1.f), 1.f);
    float tri  = fmaxf((r1+r2-d)*(d+r1-r2)*(d-r1+r2)*(d+r1+r2), 0.f);
    float lens = r1*r1*acosf(cos1) + r2*r2*acosf(cos2) - 0.5f*sqrtf(tri);
    float rmin = fminf(r1, r2);
    float inter = (d >= r1 + r2) ? 0.f
                : ((d <= fabsf(r1 - r2)) ? PIF*rmin*rmin : lens);
    return inter / (a1 + a2 - inter + EPSF);
}

__device__ __forceinline__ void decode_anchor(int a, float& ax, float& ay)
{
    if (a < 6400)      { int y = a / 80, x = a - y*80;             ax = (x+0.5f)*8.f;  ay = (y+0.5f)*8.f;  }
    else if (a < 8000) { int r = a-6400; int y = r/40, x = r-y*40; ax = (x+0.5f)*16.f; ay = (y+0.5f)*16.f; }
    else               { int r = a-8000; int y = r/20, x = r-y*20; ax = (x+0.5f)*32.f; ay = (y+0.5f)*32.f; }
}

// ============================================================
// kAB: one WARP per (b,j) GT row. Geometric candidate enumeration,
// exact top-13 (lax.top_k tie order), claim scatter.
// Also zeroes per-row maxima for this run (prev run's readers done).
// ============================================================
#define WARPS_PER_BLOCK 8

__global__ void kAB(const float* __restrict__ ps, const float* __restrict__ pc,
                    const int* __restrict__ gl, const float* __restrict__ gb,
                    const float* __restrict__ mg)
{
    const int gt_id = blockIdx.x * (WARPS_PER_BLOCK*32) + threadIdx.x;
    if (gt_id < BS*NMAX) { g_posal[gt_id] = 0u; g_posov[gt_id] = 0u; }

    const int row = blockIdx.x * WARPS_PER_BLOCK + (threadIdx.x >> 5);
    if (row >= BS*NMAX) return;
    if (!(mg[row] > 0.f)) return;              // warp-uniform
    const int lane = threadIdx.x & 31;
    const int b = row / NMAX;
    const int j = row - b*NMAX;

    const float gx = gb[row*3+0], gy = gb[row*3+1], gr = gb[row*3+2];
    int lab = gl[row]; lab = max(0, min(NC-1, lab));

    // per-scale candidate boxes
    int x0[3], y0[3], cw[3], cbase[3], ccum[3];
    const float ss[3] = {8.f, 16.f, 32.f};
    const int   nn[3] = {80, 40, 20};
    const int   bb[3] = {0, 6400, 8000};
    int total = 0;
    #pragma unroll
    for (int s = 0; s < 3; s++) {
        int xl = max(0, (int)floorf((gx - gr)/ss[s] - 0.5f));
        int xh = min(nn[s]-1, (int)ceilf ((gx + gr)/ss[s] - 0.5f));
        int yl = max(0, (int)floorf((gy - gr)/ss[s] - 0.5f));
        int yh = min(nn[s]-1, (int)ceilf ((gy + gr)/ss[s] - 0.5f));
        x0[s] = xl; y0[s] = yl;
        cw[s] = max(0, xh - xl + 1);
        int chh = max(0, yh - yl + 1);
        cbase[s] = bb[s];
        ccum[s] = total;
        total += cw[s]*chh;
    }

    // per-lane register top-13 over POSITIVE values only
    float lv[TOPK]; int li[TOPK];
    #pragma unroll
    for (int k = 0; k < TOPK; k++) { lv[k] = -1.f; li[k] = 0x7fffffff; }

    for (int i = lane; i < total; i += 32) {
        int s = (i >= ccum[2]) ? 2 : ((i >= ccum[1]) ? 1 : 0);
        int r = i - ccum[s];
        int yy = r / cw[s], xx = r - yy*cw[s];
        int gxi = x0[s] + xx, gyi = y0[s] + yy;
        float ax = (gxi + 0.5f) * ss[s];
        float ay = (gyi + 0.5f) * ss[s];
        int a = cbase[s] + gyi*nn[s] + gxi;

        float dx = gx - ax, dy = gy - ay;
        if (sqrtf(dx*dx + dy*dy) > gr) continue;

        int pa3 = (b*NA + a)*3;
        float px = pc[pa3+0], py = pc[pa3+1], pr = pc[pa3+2];
        float iou = circle_iou_f(gx, gy, gr, px, py, pr);
        float sc = ps[(b*NA + a)*NC + lab];
        float o2 = iou*iou;
        float v = sc * (o2*o2*o2);
        if (v <= 0.f) continue;                 // zeros handled analytically

        if (v > lv[TOPK-1] || (v == lv[TOPK-1] && a < li[TOPK-1])) {
            lv[TOPK-1] = v; li[TOPK-1] = a;
            #pragma unroll
            for (int k = TOPK-1; k > 0; k--) {
                bool sw = (lv[k] > lv[k-1]) || (lv[k] == lv[k-1] && li[k] < li[k-1]);
                if (sw) {
                    float tv = lv[k]; lv[k] = lv[k-1]; lv[k-1] = tv;
                    int   ti = li[k]; li[k] = li[k-1]; li[k-1] = ti;
                }
            }
        }
    }

    // warp tournament: 13 rounds; lane r keeps round-r winner
    int head = 0;
    int seli = 0x7fffffff;
    int npos = TOPK;
    for (int r = 0; r < TOPK; r++) {
        float v  = (head < TOPK) ? lv[head] : -1.f;
        int   ii = (head < TOPK) ? li[head] : 0x7fffffff;
        int   who = lane;
        #pragma unroll
        for (int off = 16; off > 0; off >>= 1) {
            float v2 = __shfl_xor_sync(0xffffffffu, v, off);
            int   i2 = __shfl_xor_sync(0xffffffffu, ii, off);
            int   w2 = __shfl_xor_sync(0xffffffffu, who, off);
            if (v2 > v || (v2 == v && i2 < ii)) { v = v2; ii = i2; who = w2; }
        }
        if (v <= 0.f) { npos = r; break; }
        if (lane == who) head++;
        if (lane == r)  seli = ii;
    }

    // gather positive indices to every lane
    int pidx[TOPK];
    for (int k = 0; k < npos; k++)
        pidx[k] = __shfl_sync(0xffffffffu, seli, k);

    // fill remaining slots: smallest global indices not among positives
    if (lane >= npos && lane < TOPK) {
        int need = lane - npos;
        int m = 0;
        while (true) {
            bool inP = false;
            for (int k = 0; k < npos; k++) if (pidx[k] == m) inP = true;
            if (!inP) { if (need == 0) break; need--; }
            m++;
        }
        seli = m;
    }

    // claim scatter for selected anchors passing the inside-GT test
    if (lane < TOPK) {
        int a = seli;
        float ax, ay;
        decode_anchor(a, ax, ay);
        float dx = gx - ax, dy = gy - ay;
        if (sqrtf(dx*dx + dy*dy) <= gr) {
            int pa = b*NA + a;
            atomicAdd(&g_cnt[pa], 1);
            atomicMax(&g_maxj[pa], NMAX - j);   // encodes min j; 0 = none
        }
    }
}

// ============================================================
// kC: per (b,a) — conflict resolution, gathers, row maxima,
//     scratch self-reset for next graph replay
// ============================================================
__global__ void kC(const float* __restrict__ ps, const float* __restrict__ pc,
                   const float* __restrict__ anc, const int* __restrict__ gl,
                   const float* __restrict__ gb, const float* __restrict__ mg,
                   float* __restrict__ out)
{
    int a = blockIdx.x * blockDim.x + threadIdx.x;
    int b = blockIdx.y;
    if (a >= NA) return;
    int pa = b * NA + a;

    float ax = anc[a*2+0], ay = anc[a*2+1];
    float px = pc[pa*3+0], py = pc[pa*3+1], pr = pc[pa*3+2];

    int cnt  = g_cnt[pa];
    int maxv = g_maxj[pa];
    if (cnt) { g_cnt[pa] = 0; g_maxj[pa] = 0; }   // reset for next replay

    int tgt, fg;
    if (cnt > 1) {
        float bov = -1.f; int jm = 0;
        for (int jj = 0; jj < NMAX; jj++) {
            int row = b * NMAX + jj;
            float ov = 0.f;
            if (mg[row] > 0.f) {
                float gx = gb[row*3+0], gy = gb[row*3+1], gr = gb[row*3+2];
                float dx = gx - ax, dy = gy - ay;
                if (sqrtf(dx*dx + dy*dy) <= gr)
                    ov = circle_iou_f(gx, gy, gr, px, py, pr);
            }
            if (ov > bov) { bov = ov; jm = jj; }
        }
        tgt = jm; fg = 1;
    } else if (cnt == 1) {
        tgt = NMAX - maxv; fg = 1;
    } else {
        tgt = 0; fg = 0;
    }

    int row = b * NMAX + tgt;
    int labRaw = gl[row];
    int labOut = max(labRaw, 0);

    out[LAB_OFF + pa] = (float)labOut;
    out[CIR_OFF + pa*3 + 0] = gb[row*3+0];
    out[CIR_OFF + pa*3 + 1] = gb[row*3+1];
    out[CIR_OFF + pa*3 + 2] = gb[row*3+2];
    out[FG_OFF  + pa] = (float)fg;
    out[TGT_OFF + pa] = (float)tgt;

    g_tgt[pa] = tgt;
    float alv = 0.f;
    int labSc = -1;
    if (fg) {
        float gx = gb[row*3+0], gy = gb[row*3+1], gr = gb[row*3+2];
        float dx = gx - ax, dy = gy - ay;
        float ov = 0.f;
        if (mg[row] > 0.f && sqrtf(dx*dx + dy*dy) <= gr)
            ov = circle_iou_f(gx, gy, gr, px, py, pr);
        int lc = max(0, min(NC-1, labRaw));
        float sc = ps[pa*NC + lc];
        float o2 = ov*ov;
        alv = sc * (o2*o2*o2);
        labSc = labOut;
        if (alv > 0.f) atomicMax(&g_posal[row], __float_as_uint(alv));
        if (ov  > 0.f) atomicMax(&g_posov[row], __float_as_uint(ov));
    }
    g_alpos[pa] = alv;
    g_lab[pa]   = labSc;
}

// ============================================================
// kF: fused target_scores — 4 float4 (64B) per thread, norm inline.
// 20 float4 per anchor = 5 groups of 4; groups never cross anchors.
// ============================================================
__global__ void kF(float* __restrict__ out)
{
    int g = blockIdx.x * blockDim.x + threadIdx.x;
    const int totalG = BS*NA*5;                   // 672,000
    if (g >= totalG) return;
    int pa = g / 5;                               // const-div (mulhi)
    int q  = g - pa*5;
    int c0 = q * 16;

    int lab = g_lab[pa];
    float nrm = 0.f;
    int rel = lab - c0;                           // valid if 0..15
    if (lab >= 0 && rel >= 0 && rel < 16) {
        int b = pa / NA;
        int row = b * NMAX + g_tgt[pa];
        float posal = __uint_as_float(g_posal[row]);
        float posov = __uint_as_float(g_posov[row]);
        nrm = g_alpos[pa] * posov / (posal + EPSF);
    } else {
        rel = -1;
    }

    float4 v0, v1, v2, v3;
    v0.x = (rel== 0)?nrm:0.f; v0.y = (rel== 1)?nrm:0.f; v0.z = (rel== 2)?nrm:0.f; v0.w = (rel== 3)?nrm:0.f;
    v1.x = (rel== 4)?nrm:0.f; v1.y = (rel== 5)?nrm:0.f; v1.z = (rel== 6)?nrm:0.f; v1.w = (rel== 7)?nrm:0.f;
    v2.x = (rel== 8)?nrm:0.f; v2.y = (rel== 9)?nrm:0.f; v2.z = (rel==10)?nrm:0.f; v2.w = (rel==11)?nrm:0.f;
    v3.x = (rel==12)?nrm:0.f; v3.y = (rel==13)?nrm:0.f; v3.z = (rel==14)?nrm:0.f; v3.w = (rel==15)?nrm:0.f;

    float4* dst = (float4*)(out + SC_OFF) + (size_t)g * 4;
    dst[0] = v0; dst[1] = v1; dst[2] = v2; dst[3] = v3;
}

// ============================================================
extern "C" void kernel_launch(void* const* d_in, const int* in_sizes, int n_in,
                              void* d_out, int out_size)
{
    const float* pd_scores  = (const float*)d_in[0];
    const float* pd_circles = (const float*)d_in[1];
    const float* anc_points = (const float*)d_in[2];
    const int*   gt_labels  = (const int*)  d_in[3];
    const float* gt_bboxes  = (const float*)d_in[4];
    const float* mask_gt    = (const float*)d_in[5];
    float* out = (float*)d_out;

    kAB<<<(BS*NMAX + WARPS_PER_BLOCK - 1)/WARPS_PER_BLOCK, 32*WARPS_PER_BLOCK>>>(
        pd_scores, pd_circles, gt_labels, gt_bboxes, mask_gt);

    dim3 gC((NA + 255)/256, BS);
    kC<<<gC, 256>>>(pd_scores, pd_circles, anc_points,
                    gt_labels, gt_bboxes, mask_gt, out);

    const int totalG = BS*NA*5;
    kF<<<(totalG + 255)/256, 256>>>(out);
}

// round 5
// speedup vs baseline: 1.1225x; 1.1225x over previous
#include <cuda_runtime.h>
#include <cuda_bf16.h>
#include <math.h>

#define BS   16
#define NA   8400
#define NMAX 64
#define NC   80
#define TOPK 13
#define EPSF 1e-9f
#define PIF  3.14159265358979323846f

// Output layout (flattened, reference return order, all f32)
#define LAB_OFF 0
#define CIR_OFF (BS*NA)                 // 134400
#define SC_OFF  (CIR_OFF + BS*NA*3)     // 537600
#define FG_OFF  (SC_OFF  + BS*NA*NC)    // 11289600
#define TGT_OFF (FG_OFF  + BS*NA)       // 11424000

typedef unsigned long long u64;

// ---- scratch (zero at module load; self-resetting across graph replays) ----
__device__ int          g_cnt [BS*NA];     // claims per anchor      (kC resets)
__device__ int          g_maxj[BS*NA];     // max(NMAX-j) of claims  (kC resets)
__device__ int          g_tgt [BS*NA];
__device__ int          g_lab [BS*NA];     // label or -1
__device__ float        g_alpos[BS*NA];
__device__ unsigned int g_posal[BS*NMAX];  // zeroed by kAB each run
__device__ unsigned int g_posov[BS*NMAX];  // zeroed by kAB each run

__device__ __forceinline__ float circle_iou_f(float gx, float gy, float gr,
                                              float px, float py, float pr)
{
    float ddx = gx - px, ddy = gy - py;
    float d  = sqrtf(ddx*ddx + ddy*ddy + EPSF);
    float r1 = gr, r2 = pr;
    float a1 = PIF*r1*r1, a2 = PIF*r2*r2;
    float d2 = d*d;
    float cos1 = fminf(fmaxf((d2 + r1*r1 - r2*r2) / (2.f*d*r1 + EPSF), -1.f), 1.f);
    float cos2 = fminf(fmaxf((d2 + r2*r2 - r1*r1) / (2.f*d*r2 + EPSF), -1.f), 1.f);
    float tri  = fmaxf((r1+r2-d)*(d+r1-r2)*(d-r1+r2)*(d+r1+r2), 0.f);
    float lens = r1*r1*acosf(cos1) + r2*r2*acosf(cos2) - 0.5f*sqrtf(tri);
    float rmin = fminf(r1, r2);
    float inter = (d >= r1 + r2) ? 0.f
                : ((d <= fabsf(r1 - r2)) ? PIF*rmin*rmin : lens);
    return inter / (a1 + a2 - inter + EPSF);
}

__device__ __forceinline__ void decode_anchor(int a, float& ax, float& ay)
{
    if (a < 6400)      { int y = a / 80, x = a - y*80;             ax = (x+0.5f)*8.f;  ay = (y+0.5f)*8.f;  }
    else if (a < 8000) { int r = a-6400; int y = r/40, x = r-y*40; ax = (x+0.5f)*16.f; ay = (y+0.5f)*16.f; }
    else               { int r = a-8000; int y = r/20, x = r-y*20; ax = (x+0.5f)*32.f; ay = (y+0.5f)*32.f; }
}

// ============================================================
// kAB: one WARP per (b,j) GT row. Geometric candidate enumeration,
// exact top-13 via 64-bit keys (value desc, index asc), claim scatter.
// NO dynamic register indexing anywhere (all arrays statically unrolled).
// ============================================================
#define KAB_WARPS 4

__global__ void __launch_bounds__(KAB_WARPS*32)
kAB(const float* __restrict__ ps, const float* __restrict__ pc,
    const int* __restrict__ gl, const float* __restrict__ gb,
    const float* __restrict__ mg)
{
    const int gt_id = blockIdx.x * (KAB_WARPS*32) + threadIdx.x;
    if (gt_id < BS*NMAX) { g_posal[gt_id] = 0u; g_posov[gt_id] = 0u; }

    const int row = blockIdx.x * KAB_WARPS + (threadIdx.x >> 5);
    if (row >= BS*NMAX) return;
    if (!(mg[row] > 0.f)) return;              // warp-uniform
    const int lane = threadIdx.x & 31;
    const int b = row / NMAX;
    const int j = row - b*NMAX;

    const float gx = gb[row*3+0], gy = gb[row*3+1], gr = gb[row*3+2];
    int lab = gl[row]; lab = max(0, min(NC-1, lab));

    // per-scale candidate boxes
    int x0[3], y0[3], cw[3], cbase[3], ccum[3];
    const float ss[3] = {8.f, 16.f, 32.f};
    const int   nn[3] = {80, 40, 20};
    const int   bb[3] = {0, 6400, 8000};
    int total = 0;
    #pragma unroll
    for (int s = 0; s < 3; s++) {
        int xl = max(0, (int)floorf((gx - gr)/ss[s] - 0.5f));
        int xh = min(nn[s]-1, (int)ceilf ((gx + gr)/ss[s] - 0.5f));
        int yl = max(0, (int)floorf((gy - gr)/ss[s] - 0.5f));
        int yh = min(nn[s]-1, (int)ceilf ((gy + gr)/ss[s] - 0.5f));
        x0[s] = xl; y0[s] = yl;
        cw[s] = max(0, xh - xl + 1);
        int chh = max(0, yh - yl + 1);
        cbase[s] = bb[s];
        ccum[s] = total;
        total += cw[s]*chh;
    }

    // per-lane sorted top-13 of 64-bit keys (desc). key=0 means empty.
    u64 k0=0,k1=0,k2=0,k3=0,k4=0,k5=0,k6=0,k7=0,k8=0,k9=0,k10=0,k11=0,k12=0;

    for (int i = lane; i < total; i += 32) {
        int s = (i >= ccum[2]) ? 2 : ((i >= ccum[1]) ? 1 : 0);
        int r = i - ccum[s];
        int yy = r / cw[s], xx = r - yy*cw[s];
        int gxi = x0[s] + xx, gyi = y0[s] + yy;
        float ax = (gxi + 0.5f) * ss[s];
        float ay = (gyi + 0.5f) * ss[s];
        int a = cbase[s] + gyi*nn[s] + gxi;

        float dx = gx - ax, dy = gy - ay;
        if (sqrtf(dx*dx + dy*dy) > gr) continue;

        int pa3 = (b*NA + a)*3;
        float px = pc[pa3+0], py = pc[pa3+1], pr = pc[pa3+2];
        float iou = circle_iou_f(gx, gy, gr, px, py, pr);
        float sc = ps[(b*NA + a)*NC + lab];
        float o2 = iou*iou;
        float v = sc * (o2*o2*o2);
        if (v <= 0.f) continue;                 // zeros handled analytically

        u64 k = ((u64)__float_as_uint(v) << 32) | (unsigned int)(~(unsigned int)a);
        // statically-unrolled insertion (sorted desc)
        if (k > k12) {
            k12 = k;
            u64 t;
            if (k12 > k11) { t=k11; k11=k12; k12=t; }
            if (k11 > k10) { t=k10; k10=k11; k11=t; }
            if (k10 > k9 ) { t=k9;  k9 =k10; k10=t; }
            if (k9  > k8 ) { t=k8;  k8 =k9;  k9 =t; }
            if (k8  > k7 ) { t=k7;  k7 =k8;  k8 =t; }
            if (k7  > k6 ) { t=k6;  k6 =k7;  k7 =t; }
            if (k6  > k5 ) { t=k5;  k5 =k6;  k6 =t; }
            if (k5  > k4 ) { t=k4;  k4 =k5;  k5 =t; }
            if (k4  > k3 ) { t=k3;  k3 =k4;  k4 =t; }
            if (k3  > k2 ) { t=k2;  k2 =k3;  k3 =t; }
            if (k2  > k1 ) { t=k1;  k1 =k2;  k2 =t; }
            if (k1  > k0 ) { t=k0;  k0 =k1;  k1 =t; }
        }
    }

    // threshold-descent selection: 13 rounds of warp-wide max below thresh
    u64 thresh = ~0ull;
    int seli = 0x7fffffff;
    int npos = TOPK;
    for (int r = 0; r < TOPK; r++) {
        u64 m = 0;
        #define SCAN(KK) { u64 kk = (KK); if (kk < thresh && kk > m) m = kk; }
        SCAN(k0) SCAN(k1) SCAN(k2) SCAN(k3) SCAN(k4) SCAN(k5) SCAN(k6)
        SCAN(k7) SCAN(k8) SCAN(k9) SCAN(k10) SCAN(k11) SCAN(k12)
        #undef SCAN
        #pragma unroll
        for (int off = 16; off > 0; off >>= 1) {
            u64 m2 = __shfl_xor_sync(0xffffffffu, m, off);
            if (m2 > m) m = m2;
        }
        if (m == 0ull) { npos = r; break; }     // warp-uniform
        if (lane == r) seli = (int)(~(unsigned int)(m & 0xffffffffu));
        thresh = m;
    }

    // gather positive indices to every lane (static unroll, predicated)
    int pidx[TOPK];
    #pragma unroll
    for (int k = 0; k < TOPK; k++)
        pidx[k] = __shfl_sync(0xffffffffu, seli, k);

    // fill remaining slots: smallest global indices not among positives
    if (lane >= npos && lane < TOPK) {
        int need = lane - npos;
        int m = 0;
        while (true) {
            bool inP = false;
            #pragma unroll
            for (int k = 0; k < TOPK; k++)
                if (k < npos && pidx[k] == m) inP = true;
            if (!inP) { if (need == 0) break; need--; }
            m++;
        }
        seli = m;
    }

    // claim scatter for selected anchors passing the inside-GT test
    if (lane < TOPK) {
        int a = seli;
        float ax, ay;
        decode_anchor(a, ax, ay);
        float dx = gx - ax, dy = gy - ay;
        if (sqrtf(dx*dx + dy*dy) <= gr) {
            int pa = b*NA + a;
            atomicAdd(&g_cnt[pa], 1);
            atomicMax(&g_maxj[pa], NMAX - j);   // encodes min j; 0 = none
        }
    }
}

// ============================================================
// kC: per (b,a) — conflict resolution, gathers, row maxima,
//     scratch self-reset for next graph replay
// ============================================================
__global__ void kC(const float* __restrict__ ps, const float* __restrict__ pc,
                   const float* __restrict__ anc, const int* __restrict__ gl,
                   const float* __restrict__ gb, const float* __restrict__ mg,
                   float* __restrict__ out)
{
    int a = blockIdx.x * blockDim.x + threadIdx.x;
    int b = blockIdx.y;
    if (a >= NA) return;
    int pa = b * NA + a;

    float ax = anc[a*2+0], ay = anc[a*2+1];
    float px = pc[pa*3+0], py = pc[pa*3+1], pr = pc[pa*3+2];

    int cnt  = g_cnt[pa];
    int maxv = g_maxj[pa];
    if (cnt) { g_cnt[pa] = 0; g_maxj[pa] = 0; }   // reset for next replay

    int tgt, fg;
    if (cnt > 1) {
        float bov = -1.f; int jm = 0;
        for (int jj = 0; jj < NMAX; jj++) {
            int row = b * NMAX + jj;
            float ov = 0.f;
            if (mg[row] > 0.f) {
                float gx = gb[row*3+0], gy = gb[row*3+1], gr = gb[row*3+2];
                float dx = gx - ax, dy = gy - ay;
                if (sqrtf(dx*dx + dy*dy) <= gr)
                    ov = circle_iou_f(gx, gy, gr, px, py, pr);
            }
            if (ov > bov) { bov = ov; jm = jj; }
        }
        tgt = jm; fg = 1;
    } else if (cnt == 1) {
        tgt = NMAX - maxv; fg = 1;
    } else {
        tgt = 0; fg = 0;
    }

    int row = b * NMAX + tgt;
    int labRaw = gl[row];
    int labOut = max(labRaw, 0);

    out[LAB_OFF + pa] = (float)labOut;
    out[CIR_OFF + pa*3 + 0] = gb[row*3+0];
    out[CIR_OFF + pa*3 + 1] = gb[row*3+1];
    out[CIR_OFF + pa*3 + 2] = gb[row*3+2];
    out[FG_OFF  + pa] = (float)fg;
    out[TGT_OFF + pa] = (float)tgt;

    g_tgt[pa] = tgt;
    float alv = 0.f;
    int labSc = -1;
    if (fg) {
        float gx = gb[row*3+0], gy = gb[row*3+1], gr = gb[row*3+2];
        float dx = gx - ax, dy = gy - ay;
        float ov = 0.f;
        if (mg[row] > 0.f && sqrtf(dx*dx + dy*dy) <= gr)
            ov = circle_iou_f(gx, gy, gr, px, py, pr);
        int lc = max(0, min(NC-1, labRaw));
        float sc = ps[pa*NC + lc];
        float o2 = ov*ov;
        alv = sc * (o2*o2*o2);
        labSc = labOut;
        if (alv > 0.f) atomicMax(&g_posal[row], __float_as_uint(alv));
        if (ov  > 0.f) atomicMax(&g_posov[row], __float_as_uint(ov));
    }
    g_alpos[pa] = alv;
    g_lab[pa]   = labSc;
}

// ============================================================
// kF: fused target_scores — 4 float4 (64B) per thread, norm inline.
// ============================================================
__global__ void kF(float* __restrict__ out)
{
    int g = blockIdx.x * blockDim.x + threadIdx.x;
    const int totalG = BS*NA*5;                   // 672,000
    if (g >= totalG) return;
    int pa = g / 5;
    int q  = g - pa*5;
    int c0 = q * 16;

    int lab = g_lab[pa];
    float nrm = 0.f;
    int rel = lab - c0;                           // valid if 0..15
    if (lab >= 0 && rel >= 0 && rel < 16) {
        int b = pa / NA;
        int row = b * NMAX + g_tgt[pa];
        float posal = __uint_as_float(g_posal[row]);
        float posov = __uint_as_float(g_posov[row]);
        nrm = g_alpos[pa] * posov / (posal + EPSF);
    } else {
        rel = -1;
    }

    float4 v0, v1, v2, v3;
    v0.x = (rel== 0)?nrm:0.f; v0.y = (rel== 1)?nrm:0.f; v0.z = (rel== 2)?nrm:0.f; v0.w = (rel== 3)?nrm:0.f;
    v1.x = (rel== 4)?nrm:0.f; v1.y = (rel== 5)?nrm:0.f; v1.z = (rel== 6)?nrm:0.f; v1.w = (rel== 7)?nrm:0.f;
    v2.x = (rel== 8)?nrm:0.f; v2.y = (rel== 9)?nrm:0.f; v2.z = (rel==10)?nrm:0.f; v2.w = (rel==11)?nrm:0.f;
    v3.x = (rel==12)?nrm:0.f; v3.y = (rel==13)?nrm:0.f; v3.z = (rel==14)?nrm:0.f; v3.w = (rel==15)?nrm:0.f;

    float4* dst = (float4*)(out + SC_OFF) + (size_t)g * 4;
    dst[0] = v0; dst[1] = v1; dst[2] = v2; dst[3] = v3;
}

// ============================================================
extern "C" void kernel_launch(void* const* d_in, const int* in_sizes, int n_in,
                              void* d_out, int out_size)
{
    const float* pd_scores  = (const float*)d_in[0];
    const float* pd_circles = (const float*)d_in[1];
    const float* anc_points = (const float*)d_in[2];
    const int*   gt_labels  = (const int*)  d_in[3];
    const float* gt_bboxes  = (const float*)d_in[4];
    const float* mask_gt    = (const float*)d_in[5];
    float* out = (float*)d_out;

    kAB<<<(BS*NMAX + KAB_WARPS - 1)/KAB_WARPS, KAB_WARPS*32>>>(
        pd_scores, pd_circles, gt_labels, gt_bboxes, mask_gt);

    dim3 gC((NA + 255)/256, BS);
    kC<<<gC, 256>>>(pd_scores, pd_circles, anc_points,
                    gt_labels, gt_bboxes, mask_gt, out);

    const int totalG = BS*NA*5;
    kF<<<(totalG + 255)/256, 256>>>(out);
}